// round 11
// baseline (speedup 1.0000x reference)
#include <cuda_runtime.h>

#define NN   8
#define CIN  4
#define COUT 64
#define DIM  512
#define RANK 4
#define BT   32
#define NT   256

typedef unsigned long long u64;

// scratch: row sums and col sums, [n][o][pos]
__device__ float g_rs[NN * COUT * DIM];
__device__ float g_cs[NN * COUT * DIM];

// ---------------------------------------------------------------------------
// packed fp32x2 helpers (sm_100+)
__device__ __forceinline__ u64 pk2(float lo, float hi) {
    u64 r; asm("mov.b64 %0,{%1,%2};" : "=l"(r) : "f"(lo), "f"(hi)); return r;
}
__device__ __forceinline__ float2 up2(u64 v) {
    float2 f; asm("mov.b64 {%0,%1},%2;" : "=f"(f.x), "=f"(f.y) : "l"(v)); return f;
}
__device__ __forceinline__ u64 dup2(float s) { return pk2(s, s); }
__device__ __forceinline__ u64 f2fma(u64 a, u64 b, u64 c) {
    u64 d; asm("fma.rn.f32x2 %0,%1,%2,%3;" : "=l"(d) : "l"(a), "l"(b), "l"(c)); return d;
}
__device__ __forceinline__ u64 f2mul(u64 a, u64 b) {
    u64 d; asm("mul.rn.f32x2 %0,%1,%2;" : "=l"(d) : "l"(a), "l"(b)); return d;
}
__device__ __forceinline__ u64 f2add(u64 a, u64 b) {
    u64 d; asm("add.rn.f32x2 %0,%1,%2;" : "=l"(d) : "l"(a), "l"(b)); return d;
}
__device__ __forceinline__ u64 shfl_xor64(u64 v, int m) {
    return __shfl_xor_sync(0xffffffffu, v, m);
}

// t2[c][dh] : lanes (w0, w0+1) of T[o,c,hg0+dh,w] = sum_r Lh[h,r]*Lw[w,r]
__device__ __forceinline__ void compute_t2(const float* __restrict__ wL, int o,
                                           int hg0, int wg0, u64 t2[CIN][2]) {
#pragma unroll
    for (int c = 0; c < CIN; c++) {
        const float* base = wL + (long)(o * CIN + c) * DIM * RANK;
        float4 lw0 = __ldg((const float4*)(base + (long)wg0 * RANK));
        float4 lw1 = __ldg((const float4*)(base + (long)(wg0 + 1) * RANK));
        float4 lh0 = __ldg((const float4*)(base + (long)hg0 * RANK));
        float4 lh1 = __ldg((const float4*)(base + (long)(hg0 + 1) * RANK));
        u64 w0p = pk2(lw0.x, lw1.x), w1p = pk2(lw0.y, lw1.y);
        u64 w2p = pk2(lw0.z, lw1.z), w3p = pk2(lw0.w, lw1.w);
        t2[c][0] = f2fma(dup2(lh0.x), w0p,
                   f2fma(dup2(lh0.y), w1p,
                   f2fma(dup2(lh0.z), w2p,
                   f2mul(dup2(lh0.w), w3p))));
        t2[c][1] = f2fma(dup2(lh1.x), w0p,
                   f2fma(dup2(lh1.y), w1p,
                   f2fma(dup2(lh1.z), w2p,
                   f2mul(dup2(lh1.w), w3p))));
    }
}

// ---------------------------------------------------------------------------
__global__ void k_zero() {
    int i = blockIdx.x * blockDim.x + threadIdx.x;
    if (i < NN * COUT * DIM) {
        g_rs[i] = 0.0f;
        g_cs[i] = 0.0f;
    }
}

// ---------------------------------------------------------------------------
// Pass 1: thread owns 2h x 2w pixels, X positive in registers (packed over w).
// Rows: 4-stage packed shuffle over 16 lanes -> 2 atomics per (group,n).
// Cols: shfl_xor(16) -> double-buffered smem stage -> 1 barrier/o -> atomics.
__global__ void __launch_bounds__(NT, 1)
k_pass1(const float* __restrict__ X, const float* __restrict__ wL) {
    __shared__ u64 stage[2][8][NN][16];   // [buf][warp][n][wpair] = 16KB

    const int tid  = threadIdx.x;
    const int gh0  = blockIdx.y * BT;
    const int gw0  = blockIdx.x * BT;
    const int h0   = (tid >> 4) << 1;
    const int w0   = (tid & 15) << 1;
    const int hg0  = gh0 + h0;
    const int wg0  = gw0 + w0;
    const int warp = tid >> 5;
    const int lane = tid & 31;

    u64 x2[NN][CIN][2];
#pragma unroll
    for (int n = 0; n < NN; n++)
#pragma unroll
        for (int c = 0; c < CIN; c++)
#pragma unroll
            for (int dh = 0; dh < 2; dh++) {
                float2 v = *(const float2*)&X[((long)(n * CIN + c) * DIM + hg0 + dh) * DIM + wg0];
                x2[n][c][dh] = pk2(v.x, v.y);
            }

#pragma unroll 1
    for (int o = 0; o < COUT; o++) {
        u64 t2[CIN][2];
        compute_t2(wL, o, hg0, wg0, t2);
        const int buf = o & 1;

#pragma unroll
        for (int n = 0; n < NN; n++) {
            u64 p0 = f2mul(x2[n][0][0], t2[0][0]);
            u64 p1 = f2mul(x2[n][0][1], t2[0][1]);
#pragma unroll
            for (int c = 1; c < CIN; c++) {
                p0 = f2fma(x2[n][c][0], t2[c][0], p0);
                p1 = f2fma(x2[n][c][1], t2[c][1], p1);
            }
            // column partials: this thread's 2 rows, then pair rows via xor16
            u64 colp = f2add(p0, p1);
            colp = f2add(colp, shfl_xor64(colp, 16));
            if (lane < 16) stage[buf][warp][n][lane] = colp;

            // row sums: lo+hi per row, packed (row h0, row h0+1), reduce 16 lanes
            float2 a = up2(p0), b = up2(p1);
            u64 rr = pk2(a.x + a.y, b.x + b.y);
            rr = f2add(rr, shfl_xor64(rr, 1));
            rr = f2add(rr, shfl_xor64(rr, 2));
            rr = f2add(rr, shfl_xor64(rr, 4));
            rr = f2add(rr, shfl_xor64(rr, 8));
            if ((lane & 15) == 0) {
                float2 r = up2(rr);
                atomicAdd(&g_rs[(n * COUT + o) * DIM + hg0],     r.x);
                atomicAdd(&g_rs[(n * COUT + o) * DIM + hg0 + 1], r.y);
            }
        }
        __syncthreads();

        if (tid < 128) {
            int n  = tid >> 4;
            int wp = tid & 15;
            u64 s = stage[buf][0][n][wp];
#pragma unroll
            for (int w_ = 1; w_ < 8; w_++)
                s = f2add(s, stage[buf][w_][n][wp]);
            float2 r = up2(s);
            atomicAdd(&g_cs[(n * COUT + o) * DIM + gw0 + 2 * wp],     r.x);
            atomicAdd(&g_cs[(n * COUT + o) * DIM + gw0 + 2 * wp + 1], r.y);
        }
    }
}

// ---------------------------------------------------------------------------
// Pass 2: barrier-free. X negated in registers; out = (cs + bias + rs) + (-P),
// all packed f32x2; diagonal handled by precomputed packed mask multiply.
__global__ void __launch_bounds__(NT, 1)
k_pass2(const float* __restrict__ X, const float* __restrict__ wL,
        const float* __restrict__ bias, float* __restrict__ out) {
    const int tid = threadIdx.x;
    const int gh0 = blockIdx.y * BT;
    const int gw0 = blockIdx.x * BT;
    const int h0  = (tid >> 4) << 1;
    const int w0  = (tid & 15) << 1;
    const int hg0 = gh0 + h0;
    const int wg0 = gw0 + w0;

    u64 xn[NN][CIN][2];   // negated X, packed over (w0, w0+1)
#pragma unroll
    for (int n = 0; n < NN; n++)
#pragma unroll
        for (int c = 0; c < CIN; c++)
#pragma unroll
            for (int dh = 0; dh < 2; dh++) {
                float2 v = *(const float2*)&X[((long)(n * CIN + c) * DIM + hg0 + dh) * DIM + wg0];
                xn[n][c][dh] = pk2(-v.x, -v.y);
            }

    u64 mask[2];
    mask[0] = pk2(hg0     == wg0 ? 0.f : 1.f, hg0     == wg0 + 1 ? 0.f : 1.f);
    mask[1] = pk2(hg0 + 1 == wg0 ? 0.f : 1.f, hg0 + 1 == wg0 + 1 ? 0.f : 1.f);

#pragma unroll 1
    for (int o = 0; o < COUT; o++) {
        u64 t2[CIN][2];
        compute_t2(wL, o, hg0, wg0, t2);
        const u64 bo2 = dup2(__ldg(&bias[o]));

#pragma unroll
        for (int n = 0; n < NN; n++) {
            const int sb = (n * COUT + o) * DIM;
            u64 cs2   = *(const u64*)&g_cs[sb + wg0];
            float2 rsv = *(const float2*)&g_rs[sb + hg0];
            u64 bb = f2add(cs2, bo2);

            // dh = 0
            u64 p = f2mul(xn[n][0][0], t2[0][0]);
            p = f2fma(xn[n][1][0], t2[1][0], p);
            p = f2fma(xn[n][2][0], t2[2][0], p);
            p = f2fma(xn[n][3][0], t2[3][0], p);
            u64 r0 = f2mul(f2add(f2add(bb, dup2(rsv.x)), p), mask[0]);
            *(u64*)&out[((long)sb + hg0) * DIM + wg0] = r0;

            // dh = 1
            p = f2mul(xn[n][0][1], t2[0][1]);
            p = f2fma(xn[n][1][1], t2[1][1], p);
            p = f2fma(xn[n][2][1], t2[2][1], p);
            p = f2fma(xn[n][3][1], t2[3][1], p);
            u64 r1 = f2mul(f2add(f2add(bb, dup2(rsv.y)), p), mask[1]);
            *(u64*)&out[((long)sb + hg0 + 1) * DIM + wg0] = r1;
        }
    }
}

// ---------------------------------------------------------------------------
extern "C" void kernel_launch(void* const* d_in, const int* in_sizes, int n_in,
                              void* d_out, int out_size) {
    const float* X    = (const float*)d_in[0];   // (8,4,512,512) f32
    const float* wL   = (const float*)d_in[1];   // (64,4,512,4)  f32
    const float* bias = (const float*)d_in[2];   // (64,)         f32
    float* out = (float*)d_out;                  // (8,64,512,512) f32

    k_zero<<<(NN * COUT * DIM + NT - 1) / NT, NT>>>();

    dim3 grid(DIM / BT, DIM / BT);   // (16, 16)
    k_pass1<<<grid, NT>>>(X, wL);
    k_pass2<<<grid, NT>>>(X, wL, bias, out);
}

// round 16
// speedup vs baseline: 1.2243x; 1.2243x over previous
#include <cuda_runtime.h>

#define NN   8
#define CIN  4
#define COUT 64
#define DIM  512
#define RANK 4
#define BT   32
#define NT   512
#define OG   8        // o-group for L staging

typedef unsigned long long u64;

// scratch: row sums and col sums, [n][o][pos]
__device__ float g_rs[NN * COUT * DIM];
__device__ float g_cs[NN * COUT * DIM];

// ---------------------------------------------------------------------------
// packed fp32x2 helpers (sm_100+)
__device__ __forceinline__ u64 pk2(float lo, float hi) {
    u64 r; asm("mov.b64 %0,{%1,%2};" : "=l"(r) : "f"(lo), "f"(hi)); return r;
}
__device__ __forceinline__ float2 up2(u64 v) {
    float2 f; asm("mov.b64 {%0,%1},%2;" : "=f"(f.x), "=f"(f.y) : "l"(v)); return f;
}
__device__ __forceinline__ u64 dup2(float s) { return pk2(s, s); }
__device__ __forceinline__ u64 f2fma(u64 a, u64 b, u64 c) {
    u64 d; asm("fma.rn.f32x2 %0,%1,%2,%3;" : "=l"(d) : "l"(a), "l"(b), "l"(c)); return d;
}
__device__ __forceinline__ u64 f2mul(u64 a, u64 b) {
    u64 d; asm("mul.rn.f32x2 %0,%1,%2;" : "=l"(d) : "l"(a), "l"(b)); return d;
}
__device__ __forceinline__ u64 f2add(u64 a, u64 b) {
    u64 d; asm("add.rn.f32x2 %0,%1,%2;" : "=l"(d) : "l"(a), "l"(b)); return d;
}
__device__ __forceinline__ u64 shfl_xor64(u64 v, int m) {
    return __shfl_xor_sync(0xffffffffu, v, m);
}

// ---------------------------------------------------------------------------
__global__ void k_zero() {
    int i = blockIdx.x * blockDim.x + threadIdx.x;
    if (i < NN * COUT * DIM) {
        g_rs[i] = 0.0f;
        g_cs[i] = 0.0f;
    }
}

// ---------------------------------------------------------------------------
// Stage L for OG consecutive o's: Lh from rows [gp0, gp0+32) of the h-tile,
// Lw from the w-tile. Layout: L[og][c*128 + pos*4 + r]. 1024 float4 per array.
__device__ __forceinline__ void stage_L(const float* __restrict__ wL, int og0,
                                        int gh0, int gw0,
                                        float (*Lh)[CIN * BT * RANK],
                                        float (*Lw)[CIN * BT * RANK], int tid) {
#pragma unroll
    for (int k = tid; k < OG * 128; k += NT) {
        int og  = k >> 7;
        int rem = k & 127;
        int c   = rem >> 5;
        int pos = rem & 31;
        long rowbase = (long)((og0 + og) * CIN + c) * DIM;
        ((float4*)Lh[og])[rem] = *(const float4*)(wL + (rowbase + gh0 + pos) * RANK);
        ((float4*)Lw[og])[rem] = *(const float4*)(wL + (rowbase + gw0 + pos) * RANK);
    }
}

// ---------------------------------------------------------------------------
// Pass 1: warp W owns rows (W, W+16), lane = w. P packed over rows (u64).
// Row sums: 9-shuffle folding butterfly over 8 n-values; col sums: smem stage
// (double-buffered) + cross-warp reduce; 1 barrier per o.
__global__ void __launch_bounds__(NT, 1)
k_pass1(const float* __restrict__ X, const float* __restrict__ wL) {
    __shared__ float Lh[OG][CIN * BT * RANK];     // 16KB
    __shared__ float Lw[OG][CIN * BT * RANK];     // 16KB
    __shared__ float cs_sm[2][16][NN][BT];        // 32KB

    const int tid  = threadIdx.x;
    const int gh0  = blockIdx.y * BT;
    const int gw0  = blockIdx.x * BT;
    const int lane = tid & 31;
    const int W    = tid >> 5;

    // X packed over rows (W, W+16)
    u64 x01[NN][CIN];
#pragma unroll
    for (int n = 0; n < NN; n++)
#pragma unroll
        for (int c = 0; c < CIN; c++) {
            const float* p = X + ((long)(n * CIN + c) * DIM + gh0) * DIM + gw0 + lane;
            x01[n][c] = pk2(p[(long)W * DIM], p[(long)(W + 16) * DIM]);
        }

    for (int og0 = 0; og0 < COUT; og0 += OG) {
        __syncthreads();                       // previous group fully consumed
        stage_L(wL, og0, gh0, gw0, Lh, Lw, tid);
        __syncthreads();

#pragma unroll 1
        for (int oi = 0; oi < OG; oi++) {
            const int o   = og0 + oi;
            const int buf = o & 1;

            // t packed over rows: t01[c] = (T[o,c,W,lane], T[o,c,W+16,lane])
            u64 t01[CIN];
#pragma unroll
            for (int c = 0; c < CIN; c++) {
                float4 lw  = *(const float4*)&Lw[oi][(c * BT + lane) * 4];
                float4 lh0 = *(const float4*)&Lh[oi][(c * BT + W) * 4];
                float4 lh1 = *(const float4*)&Lh[oi][(c * BT + W + 16) * 4];
                float t0 = lh0.x * lw.x + lh0.y * lw.y + lh0.z * lw.z + lh0.w * lw.w;
                float t1 = lh1.x * lw.x + lh1.y * lw.y + lh1.z * lw.z + lh1.w * lw.w;
                t01[c] = pk2(t0, t1);
            }

            u64 u[NN];
#pragma unroll
            for (int n = 0; n < NN; n++) {
                u64 p = f2mul(x01[n][0], t01[0]);
                p = f2fma(x01[n][1], t01[1], p);
                p = f2fma(x01[n][2], t01[2], p);
                p = f2fma(x01[n][3], t01[3], p);
                u[n] = p;                                   // (rowA, rowB)
                float2 pf = up2(p);
                cs_sm[buf][W][n][lane] = pf.x + pf.y;       // col partial
            }

            // folding butterfly: 8 u64 values reduced over 32 lanes
#pragma unroll
            for (int i = 0; i < 4; i++) {
                u64 x = (lane & 16) ? u[i] : u[i + 4];
                u64 y = shfl_xor64(x, 16);
                u64 z = (lane & 16) ? u[i + 4] : u[i];
                u[i] = f2add(y, z);
            }
#pragma unroll
            for (int i = 0; i < 2; i++) {
                u64 x = (lane & 8) ? u[i] : u[i + 2];
                u64 y = shfl_xor64(x, 8);
                u64 z = (lane & 8) ? u[i + 2] : u[i];
                u[i] = f2add(y, z);
            }
            {
                u64 x = (lane & 4) ? u[0] : u[1];
                u64 y = shfl_xor64(x, 4);
                u64 z = (lane & 4) ? u[1] : u[0];
                u[0] = f2add(y, z);
            }
            u[0] = f2add(u[0], shfl_xor64(u[0], 2));
            u[0] = f2add(u[0], shfl_xor64(u[0], 1));

            if ((lane & 3) == 0) {
                int n = lane >> 2;                           // 0..7
                float2 r = up2(u[0]);
                atomicAdd(&g_rs[(n * COUT + o) * DIM + gh0 + W],      r.x);
                atomicAdd(&g_rs[(n * COUT + o) * DIM + gh0 + W + 16], r.y);
            }

            __syncthreads();                                 // cs_sm[buf] ready
            if (tid < NN * BT) {
                int n  = tid >> 5;
                int ww = tid & 31;
                float s = cs_sm[buf][0][n][ww];
#pragma unroll
                for (int Wp = 1; Wp < 16; Wp++)
                    s += cs_sm[buf][Wp][n][ww];
                atomicAdd(&g_cs[(n * COUT + o) * DIM + gw0 + ww], s);
            }
            // no trailing sync: double-buffered cs_sm; next iteration's sync
            // orders this reduce before buf reuse at o+2.
        }
    }
}

// ---------------------------------------------------------------------------
// Pass 2: thread = (h, w-pair). X negated/packed in regs; t from smem L;
// rs/cs read direct from L2-resident scratch; packed epilogue + mask;
// only 2 barriers per 8-o group.
__global__ void __launch_bounds__(NT, 1)
k_pass2(const float* __restrict__ X, const float* __restrict__ wL,
        const float* __restrict__ bias, float* __restrict__ out) {
    __shared__ float Lh[OG][CIN * BT * RANK];     // 16KB
    __shared__ float Lw[OG][CIN * BT * RANK];     // 16KB

    const int tid = threadIdx.x;
    const int gh0 = blockIdx.y * BT;
    const int gw0 = blockIdx.x * BT;
    const int h   = tid >> 4;
    const int w0  = (tid & 15) * 2;
    const int hg  = gh0 + h;
    const int wg0 = gw0 + w0;

    u64 xn[NN][CIN];   // negated X, packed over (w0, w0+1)
#pragma unroll
    for (int n = 0; n < NN; n++)
#pragma unroll
        for (int c = 0; c < CIN; c++) {
            float2 v = *(const float2*)&X[((long)(n * CIN + c) * DIM + hg) * DIM + wg0];
            xn[n][c] = pk2(-v.x, -v.y);
        }

    const u64 mask = pk2(hg == wg0 ? 0.f : 1.f, hg == wg0 + 1 ? 0.f : 1.f);

    for (int og0 = 0; og0 < COUT; og0 += OG) {
        __syncthreads();
        stage_L(wL, og0, gh0, gw0, Lh, Lw, tid);
        __syncthreads();

#pragma unroll 1
        for (int oi = 0; oi < OG; oi++) {
            const int o = og0 + oi;

            u64 t2[CIN];
#pragma unroll
            for (int c = 0; c < CIN; c++) {
                float4 lh  = *(const float4*)&Lh[oi][(c * BT + h) * 4];
                float4 lw0 = *(const float4*)&Lw[oi][(c * BT + w0) * 4];
                float4 lw1 = *(const float4*)&Lw[oi][(c * BT + w0 + 1) * 4];
                t2[c] = f2fma(dup2(lh.x), pk2(lw0.x, lw1.x),
                        f2fma(dup2(lh.y), pk2(lw0.y, lw1.y),
                        f2fma(dup2(lh.z), pk2(lw0.z, lw1.z),
                        f2mul(dup2(lh.w), pk2(lw0.w, lw1.w)))));
            }

            const u64 bo2 = dup2(__ldg(&bias[o]));

#pragma unroll
            for (int n = 0; n < NN; n++) {
                const int sb = (n * COUT + o) * DIM;
                u64 cs2    = *(const u64*)&g_cs[sb + wg0];
                float rsv  = __ldg(&g_rs[sb + hg]);
                u64 base   = f2add(cs2, f2add(bo2, dup2(rsv)));

                u64 p = f2mul(xn[n][0], t2[0]);             // -P accumulates
                p = f2fma(xn[n][1], t2[1], p);
                p = f2fma(xn[n][2], t2[2], p);
                p = f2fma(xn[n][3], t2[3], p);

                u64 r = f2mul(f2add(base, p), mask);
                *(u64*)&out[((long)sb + hg) * DIM + wg0] = r;
            }
        }
    }
}

// ---------------------------------------------------------------------------
extern "C" void kernel_launch(void* const* d_in, const int* in_sizes, int n_in,
                              void* d_out, int out_size) {
    const float* X    = (const float*)d_in[0];   // (8,4,512,512) f32
    const float* wL   = (const float*)d_in[1];   // (64,4,512,4)  f32
    const float* bias = (const float*)d_in[2];   // (64,)         f32
    float* out = (float*)d_out;                  // (8,64,512,512) f32

    k_zero<<<(NN * COUT * DIM + NT - 1) / NT, NT>>>();

    dim3 grid(DIM / BT, DIM / BT);   // (16, 16)
    k_pass1<<<grid, NT>>>(X, wL);
    k_pass2<<<grid, NT>>>(X, wL, bias, out);
}

// round 17
// speedup vs baseline: 1.6479x; 1.3460x over previous
#include <cuda_runtime.h>

#define NN   8
#define CIN  4
#define COUT 64
#define DIM  512
#define RANK 4
#define BT   32
#define NT   512
#define NTILE (DIM / BT)   // 16

typedef unsigned long long u64;

// final row/col sums [n][o][pos]
__device__ float g_rs[NN * COUT * DIM];
__device__ float g_cs[NN * COUT * DIM];
// per-tile partials [n][o][pos][tile]  (16.8 MB each, static)
__device__ float g_rs_part[NN * COUT * DIM * NTILE];
__device__ float g_cs_part[NN * COUT * DIM * NTILE];

// ---------------------------------------------------------------------------
// packed fp32x2 helpers (sm_100+)
__device__ __forceinline__ u64 pk2(float lo, float hi) {
    u64 r; asm("mov.b64 %0,{%1,%2};" : "=l"(r) : "f"(lo), "f"(hi)); return r;
}
__device__ __forceinline__ float2 up2(u64 v) {
    float2 f; asm("mov.b64 {%0,%1},%2;" : "=f"(f.x), "=f"(f.y) : "l"(v)); return f;
}
__device__ __forceinline__ u64 f2fma(u64 a, u64 b, u64 c) {
    u64 d; asm("fma.rn.f32x2 %0,%1,%2,%3;" : "=l"(d) : "l"(a), "l"(b), "l"(c)); return d;
}
__device__ __forceinline__ u64 f2mul(u64 a, u64 b) {
    u64 d; asm("mul.rn.f32x2 %0,%1,%2;" : "=l"(d) : "l"(a), "l"(b)); return d;
}
__device__ __forceinline__ u64 f2add(u64 a, u64 b) {
    u64 d; asm("add.rn.f32x2 %0,%1,%2;" : "=l"(d) : "l"(a), "l"(b)); return d;
}
__device__ __forceinline__ u64 shfl_xor64(u64 v, int m) {
    return __shfl_xor_sync(0xffffffffu, v, m);
}

// ---------------------------------------------------------------------------
// Pass 1: warp W owns rows (W, W+16), lane = w. P packed over rows in u64.
// Row sums: 9-shuffle folding butterfly over the 8 n-values, then plain
// stores into per-tile partial slots (no atomics). Col sums: smem stage +
// cross-warp reduce, stored into partial slots.
__global__ void __launch_bounds__(NT, 1)
k_pass1(const float* __restrict__ X, const float* __restrict__ wL) {
    __shared__ float Lh[CIN * BT * RANK];       // 512
    __shared__ float Lw[CIN * BT * RANK];       // 512
    __shared__ float cs_sm[16][NN][BT];         // 16KB

    const int tid  = threadIdx.x;
    const int ht   = blockIdx.y;
    const int wt   = blockIdx.x;
    const int gh0  = ht * BT;
    const int gw0  = wt * BT;
    const int lane = tid & 31;
    const int W    = tid >> 5;                  // warp 0..15, owns rows W, W+16

    // X packed over rows (W, W+16): 64 registers
    u64 x01[NN][CIN];
#pragma unroll
    for (int n = 0; n < NN; n++)
#pragma unroll
        for (int c = 0; c < CIN; c++) {
            const float* p = X + ((long)(n * CIN + c) * DIM + gh0) * DIM + gw0 + lane;
            x01[n][c] = pk2(p[(long)W * DIM], p[(long)(W + 16) * DIM]);
        }

#pragma unroll 1
    for (int o = 0; o < COUT; o++) {
        // stage L rows for this tile (1 float per thread, coalesced per c)
        {
            int c = tid >> 7;
            int i = (tid >> 2) & 31;
            int r = tid & 3;
            Lh[tid] = wL[((o * CIN + c) * DIM + gh0 + i) * RANK + r];
            Lw[tid] = wL[((o * CIN + c) * DIM + gw0 + i) * RANK + r];
        }
        __syncthreads();

        // t packed over rows: t01[c] = (T[o,c,W,lane], T[o,c,W+16,lane])
        u64 t01[CIN];
#pragma unroll
        for (int c = 0; c < CIN; c++) {
            float4 lw  = *(const float4*)&Lw[(c * BT + lane) * 4];
            float4 lh0 = *(const float4*)&Lh[(c * BT + W) * 4];        // broadcast
            float4 lh1 = *(const float4*)&Lh[(c * BT + W + 16) * 4];   // broadcast
            float t0 = lh0.x * lw.x + lh0.y * lw.y + lh0.z * lw.z + lh0.w * lw.w;
            float t1 = lh1.x * lw.x + lh1.y * lw.y + lh1.z * lw.z + lh1.w * lw.w;
            t01[c] = pk2(t0, t1);
        }

        u64 u[NN];
#pragma unroll
        for (int n = 0; n < NN; n++) {
            u64 p = f2mul(x01[n][0], t01[0]);
            p = f2fma(x01[n][1], t01[1], p);
            p = f2fma(x01[n][2], t01[2], p);
            p = f2fma(x01[n][3], t01[3], p);
            u[n] = p;                                   // (rowW, rowW+16)
            float2 pf = up2(p);
            cs_sm[W][n][lane] = pf.x + pf.y;            // col partial (2 rows)
        }

        // folding butterfly: 8 u64 values reduced over 32 lanes -> lane 4n
#pragma unroll
        for (int i = 0; i < 4; i++) {
            u64 x = (lane & 16) ? u[i] : u[i + 4];
            u64 y = shfl_xor64(x, 16);
            u64 z = (lane & 16) ? u[i + 4] : u[i];
            u[i] = f2add(y, z);
        }
#pragma unroll
        for (int i = 0; i < 2; i++) {
            u64 x = (lane & 8) ? u[i] : u[i + 2];
            u64 y = shfl_xor64(x, 8);
            u64 z = (lane & 8) ? u[i + 2] : u[i];
            u[i] = f2add(y, z);
        }
        {
            u64 x = (lane & 4) ? u[0] : u[1];
            u64 y = shfl_xor64(x, 4);
            u64 z = (lane & 4) ? u[1] : u[0];
            u[0] = f2add(y, z);
        }
        u[0] = f2add(u[0], shfl_xor64(u[0], 2));
        u[0] = f2add(u[0], shfl_xor64(u[0], 1));

        if ((lane & 3) == 0) {
            int n = lane >> 2;                           // 0..7
            float2 r = up2(u[0]);
            long base = ((long)(n * COUT + o) * DIM) * NTILE;
            g_rs_part[base + (long)(gh0 + W)      * NTILE + wt] = r.x;
            g_rs_part[base + (long)(gh0 + W + 16) * NTILE + wt] = r.y;
        }

        __syncthreads();                                 // cs_sm ready
        if (tid < NN * BT) {
            int n  = tid >> 5;
            int ww = tid & 31;
            float s = cs_sm[0][n][ww];
#pragma unroll
            for (int Wp = 1; Wp < 16; Wp++)
                s += cs_sm[Wp][n][ww];
            g_cs_part[((long)(n * COUT + o) * DIM + gw0 + ww) * NTILE + ht] = s;
        }
        __syncthreads();
    }
}

// ---------------------------------------------------------------------------
// Reduce 16 per-tile partials -> final g_rs / g_cs. 524288 outputs.
__global__ void __launch_bounds__(NT)
k_reduce() {
    int i = blockIdx.x * blockDim.x + threadIdx.x;       // 0 .. 2*262144-1
    const int HALF = NN * COUT * DIM;
    bool is_cs = i >= HALF;
    int j = is_cs ? i - HALF : i;
    const float4* src = (const float4*)((is_cs ? g_cs_part : g_rs_part) + (long)j * NTILE);
    float4 a = src[0], b = src[1], c = src[2], d = src[3];
    float s = (a.x + a.y + a.z + a.w) + (b.x + b.y + b.z + b.w)
            + (c.x + c.y + c.z + c.w) + (d.x + d.y + d.z + d.w);
    if (is_cs) g_cs[j] = s; else g_rs[j] = s;
}

// ---------------------------------------------------------------------------
// Pass 2: identical to the proven R8 version. X in registers; rs/cs tile
// staged in smem per o; float2 stores.
__global__ void __launch_bounds__(NT)
k_pass2(const float* __restrict__ X, const float* __restrict__ wL,
        const float* __restrict__ bias, float* __restrict__ out) {
    __shared__ float Lh[CIN * BT * RANK];    // 512
    __shared__ float Lw[CIN * BT * RANK];    // 512
    __shared__ float rs_sm[NN * BT];         // 256: [n][h]
    __shared__ float cs_sm[NN * BT];         // 256: [n][w]

    const int tid = threadIdx.x;
    const int gh0 = blockIdx.y * BT;
    const int gw0 = blockIdx.x * BT;
    const int h   = tid >> 4;
    const int w0  = (tid & 15) * 2;
    const int hg  = gh0 + h;

    float xa[NN][CIN], xb[NN][CIN];
#pragma unroll
    for (int n = 0; n < NN; n++)
#pragma unroll
        for (int c = 0; c < CIN; c++) {
            float2 v = *(const float2*)&X[((long)(n * CIN + c) * DIM + hg) * DIM + gw0 + w0];
            xa[n][c] = v.x;
            xb[n][c] = v.y;
        }

#pragma unroll 1
    for (int o = 0; o < COUT; o++) {
        {
            int c = tid >> 7;
            int i = (tid >> 2) & 31;
            int r = tid & 3;
            Lh[tid] = wL[((o * CIN + c) * DIM + gh0 + i) * RANK + r];
            Lw[tid] = wL[((o * CIN + c) * DIM + gw0 + i) * RANK + r];
        }
        {
            int n = tid >> 6;
            int i = tid & 63;
            int base = (n * COUT + o) * DIM;
            if (i < 32) rs_sm[n * BT + i]        = g_rs[base + gh0 + i];
            else        cs_sm[n * BT + (i - 32)] = g_cs[base + gw0 + (i - 32)];
        }
        __syncthreads();

        float tA[CIN], tB[CIN];
#pragma unroll
        for (int c = 0; c < CIN; c++) {
            float4 lh  = *(const float4*)&Lh[(c * BT + h) * 4];
            float4 lwA = *(const float4*)&Lw[(c * BT + w0) * 4];
            float4 lwB = *(const float4*)&Lw[(c * BT + w0 + 1) * 4];
            tA[c] = lh.x * lwA.x + lh.y * lwA.y + lh.z * lwA.z + lh.w * lwA.w;
            tB[c] = lh.x * lwB.x + lh.y * lwB.y + lh.z * lwB.z + lh.w * lwB.w;
        }

        const float bo = __ldg(&bias[o]);

#pragma unroll
        for (int n = 0; n < NN; n++) {
            float pA = xa[n][0] * tA[0] + xa[n][1] * tA[1]
                     + xa[n][2] * tA[2] + xa[n][3] * tA[3];
            float pB = xb[n][0] * tB[0] + xb[n][1] * tB[1]
                     + xb[n][2] * tB[2] + xb[n][3] * tB[3];

            float rsv = rs_sm[n * BT + h];
            float csA = cs_sm[n * BT + w0];
            float csB = cs_sm[n * BT + w0 + 1];

            float oA = rsv + csA - pA + bo;
            float oB = rsv + csB - pB + bo;
            if (hg == gw0 + w0)     oA = 0.0f;
            if (hg == gw0 + w0 + 1) oB = 0.0f;

            *(float2*)&out[((long)(n * COUT + o) * DIM + hg) * DIM + gw0 + w0]
                = make_float2(oA, oB);
        }
        __syncthreads();
    }
}

// ---------------------------------------------------------------------------
extern "C" void kernel_launch(void* const* d_in, const int* in_sizes, int n_in,
                              void* d_out, int out_size) {
    const float* X    = (const float*)d_in[0];   // (8,4,512,512) f32
    const float* wL   = (const float*)d_in[1];   // (64,4,512,4)  f32
    const float* bias = (const float*)d_in[2];   // (64,)         f32
    float* out = (float*)d_out;                  // (8,64,512,512) f32

    dim3 grid(DIM / BT, DIM / BT);   // (16, 16)
    k_pass1<<<grid, NT>>>(X, wL);
    k_reduce<<<(2 * NN * COUT * DIM) / NT, NT>>>();
    k_pass2<<<grid, NT>>>(X, wL, bias, out);
}